// round 15
// baseline (speedup 1.0000x reference)
#include <cuda_runtime.h>
#include <cuda_bf16.h>

#define B_DIM 512
#define P_DIM 512
#define F_DIM 1024
#define EPS_T 1e-8f

#define SPLITK 16
#define NTILES 64                   // 8x8 tiles of 64x64
#define NUNITS (NTILES * SPLITK)    // 1024
#define GRID_MAIN 444               // 3 CTAs/SM x 148
#define QSCALE 2047.0f              // 11-bit: 32 adds/lane stay < 2^16
#define KPITCH 72                   // smem row pitch in u16 (144B)

// Scratch (static device globals — no allocation allowed)
__device__ __align__(16) unsigned short g_qx[B_DIM * F_DIM];  // u11-in-u16 sigmoid(x)
__device__ __align__(16) unsigned short g_qw[P_DIM * F_DIM];  // u11-in-u16 sigmoid(w)
__device__ __align__(16) float g_S[B_DIM + P_DIM];            // fp32 row sums of q
__device__ float g_part[SPLITK * B_DIM * P_DIM];              // split-K partials
__device__ int   g_ctr;                                       // work counter

// ---------------------------------------------------------------------------
__device__ __forceinline__ float sigmoid_fast(float x)
{
    float t;
    asm("tanh.approx.f32 %0, %1;" : "=f"(t) : "f"(x * 0.5f));
    return fmaf(0.5f, t, 0.5f);
}

__device__ __forceinline__ unsigned minu16x2(unsigned a, unsigned b)
{
    unsigned d;
    asm("min.u16x2 %0, %1, %2;" : "=r"(d) : "r"(a), "r"(b));
    return d;
}

__device__ __forceinline__ void cp16(void* smem_dst, const void* gsrc)
{
    unsigned sdst = (unsigned)__cvta_generic_to_shared(smem_dst);
    asm volatile("cp.async.cg.shared.global [%0], [%1], 16;"
                 :: "r"(sdst), "l"(gsrc));
}

// ---------------------------------------------------------------------------
// Kernel 1: sigmoid (tanh.approx.f32) -> u11 quantize (stored u16) + row sums
// of q (exact small ints in fp32). One block per row; resets g_ctr.
// ---------------------------------------------------------------------------
__global__ __launch_bounds__(256) void prep_kernel(
    const float* __restrict__ x, const float* __restrict__ w)
{
    if (blockIdx.x == 0 && threadIdx.x == 0) g_ctr = GRID_MAIN;

    int row = blockIdx.x;                 // 0..1023 combined
    int tid = threadIdx.x;

    const float* src;
    unsigned short* dq;
    if (row < B_DIM) {
        src = x + (size_t)row * F_DIM;
        dq  = g_qx + (size_t)row * F_DIM;
    } else {
        src = w + (size_t)(row - B_DIM) * F_DIM;
        dq  = g_qw + (size_t)(row - B_DIM) * F_DIM;
    }

    float4 v = reinterpret_cast<const float4*>(src)[tid];
    float s0 = sigmoid_fast(v.x);
    float s1 = sigmoid_fast(v.y);
    float s2 = sigmoid_fast(v.z);
    float s3 = sigmoid_fast(v.w);

    unsigned q0 = __float2uint_rn(s0 * QSCALE);
    unsigned q1 = __float2uint_rn(s1 * QSCALE);
    unsigned q2 = __float2uint_rn(s2 * QSCALE);
    unsigned q3 = __float2uint_rn(s3 * QSCALE);
    reinterpret_cast<uint2*>(dq)[tid] = make_uint2(q0 | (q1 << 16), q2 | (q3 << 16));

    float local = (float)((q0 + q1) + (q2 + q3));   // exact (small ints)
    #pragma unroll
    for (int o = 16; o > 0; o >>= 1)
        local += __shfl_xor_sync(0xFFFFFFFFu, local, o);

    __shared__ float red[8];
    if ((tid & 31) == 0) red[tid >> 5] = local;
    __syncthreads();
    if (tid == 0) {
        float t = 0.f;
        #pragma unroll
        for (int i = 0; i < 8; i++) t += red[i];
        g_S[row] = t;     // in q units
    }
}

// ---------------------------------------------------------------------------
// Kernel 2: persistent min-sum: min.u16x2 (alu) + packed u32 add (IMAD/IADD3,
// pipe-balanced by ptxas). Lane-overflow-safe: 32 adds x 2047 < 2^16.
// Dynamic queue, cp.async double buffer, one barrier per unit.
// Unit = 64x64 tile x KC=64 k. 1024 units, grid 444 x 256, 3 CTAs/SM.
// ---------------------------------------------------------------------------
__global__ __launch_bounds__(256, 3) void tversky_main_kernel()
{
    __shared__ __align__(16) unsigned short xs[2][64][KPITCH];
    __shared__ __align__(16) unsigned short ws[2][64][KPITCH];
    __shared__ int s_uu[2];

    int tid = threadIdx.x;
    int tx = tid & 15;            // N: tx + 16j
    int ty = tid >> 4;            // M: ty + 16i
    int r0 = tid >> 3;            // loader row 0..31 (also r0+32)
    int seg = tid & 7;            // 16B segment

    const uint4* xg4 = reinterpret_cast<const uint4*>(g_qx);
    const uint4* wg4 = reinterpret_cast<const uint4*>(g_qw);

    int u = blockIdx.x;           // static first unit; g_ctr starts at GRID_MAIN
    int cur = 0;

    {   // prologue: stage unit u into buf 0 via cp.async
        int tile = u >> 4, split = u & 15;
        int m0 = (tile >> 3) << 6, n0 = (tile & 7) << 6;
        int kb4 = split << 3;
        cp16(&xs[0][r0][seg * 8],      xg4 + (m0 + r0) * 128 + kb4 + seg);
        cp16(&xs[0][r0 + 32][seg * 8], xg4 + (m0 + r0 + 32) * 128 + kb4 + seg);
        cp16(&ws[0][r0][seg * 8],      wg4 + (n0 + r0) * 128 + kb4 + seg);
        cp16(&ws[0][r0 + 32][seg * 8], wg4 + (n0 + r0 + 32) * 128 + kb4 + seg);
        asm volatile("cp.async.commit_group;" ::: "memory");
    }

    while (u < NUNITS) {
        if (tid == 0) s_uu[cur] = atomicAdd(&g_ctr, 1);
        asm volatile("cp.async.wait_group 0;" ::: "memory");
        __syncthreads();          // buf(cur) complete everywhere; s_uu[cur] visible
        int un = s_uu[cur];

        if (un < NUNITS) {        // stage next unit into other buffer (async)
            int tile = un >> 4, split = un & 15;
            int m0 = (tile >> 3) << 6, n0 = (tile & 7) << 6;
            int kb4 = split << 3;
            int nb = cur ^ 1;
            cp16(&xs[nb][r0][seg * 8],      xg4 + (m0 + r0) * 128 + kb4 + seg);
            cp16(&xs[nb][r0 + 32][seg * 8], xg4 + (m0 + r0 + 32) * 128 + kb4 + seg);
            cp16(&ws[nb][r0][seg * 8],      wg4 + (n0 + r0) * 128 + kb4 + seg);
            cp16(&ws[nb][r0 + 32][seg * 8], wg4 + (n0 + r0 + 32) * 128 + kb4 + seg);
            asm volatile("cp.async.commit_group;" ::: "memory");
        }

        unsigned acc[4][4];       // packed u16x2 lane sums (overflow-free)
        #pragma unroll
        for (int i = 0; i < 4; i++)
            #pragma unroll
            for (int j = 0; j < 4; j++) acc[i][j] = 0u;

        {   // compute: 64 k of u16 per unit, 8 per chunk
            const unsigned short (*xb)[KPITCH] = xs[cur];
            const unsigned short (*wb)[KPITCH] = ws[cur];
            #pragma unroll 2
            for (int c = 0; c < 8; c++) {
                uint4 xq[4], wq[4];
                #pragma unroll
                for (int i = 0; i < 4; i++)
                    xq[i] = *reinterpret_cast<const uint4*>(&xb[ty + 16 * i][c * 8]);
                #pragma unroll
                for (int j = 0; j < 4; j++)
                    wq[j] = *reinterpret_cast<const uint4*>(&wb[tx + 16 * j][c * 8]);
                #pragma unroll
                for (int i = 0; i < 4; i++)
                    #pragma unroll
                    for (int j = 0; j < 4; j++) {
                        acc[i][j] += minu16x2(xq[i].x, wq[j].x);
                        acc[i][j] += minu16x2(xq[i].y, wq[j].y);
                        acc[i][j] += minu16x2(xq[i].z, wq[j].z);
                        acc[i][j] += minu16x2(xq[i].w, wq[j].w);
                    }
            }
        }

        // write split-K partials for unit u: unpack lanes (exact) -> fp32
        {
            int tile = u >> 4, split = u & 15;
            int m0 = (tile >> 3) << 6, n0 = (tile & 7) << 6;
            float* pbase = g_part + ((size_t)split * B_DIM + m0) * P_DIM + n0;
            #pragma unroll
            for (int i = 0; i < 4; i++)
                #pragma unroll
                for (int j = 0; j < 4; j++) {
                    unsigned p = acc[i][j];
                    pbase[(size_t)(ty + 16 * i) * P_DIM + tx + 16 * j] =
                        (float)((p & 0xFFFFu) + (p >> 16));
                }
        }

        u = un;
        cur ^= 1;
    }
}

// ---------------------------------------------------------------------------
// Kernel 3: combine 16 split-K partials (scale 1/2047) + Tversky epilogue.
//   out = I / (I + alpha*(Sx-I) + beta*(Sw-I) + eps) + bias
// ---------------------------------------------------------------------------
__global__ __launch_bounds__(256) void finalize_kernel(
    const float* __restrict__ bias,
    const float* __restrict__ alpha,
    const float* __restrict__ beta,
    float* __restrict__ out)
{
    int t4 = blockIdx.x * 256 + threadIdx.x;   // float4 id, 0..65535
    int m  = t4 >> 7;
    int n4 = t4 & 127;

    const float4* pp = reinterpret_cast<const float4*>(g_part) + t4;
    float4 I = make_float4(0.f, 0.f, 0.f, 0.f);
    #pragma unroll
    for (int s = 0; s < SPLITK; s++) {
        float4 v = pp[(size_t)s * (B_DIM * P_DIM / 4)];
        I.x += v.x; I.y += v.y; I.z += v.z; I.w += v.w;
    }
    const float inv = 1.0f / QSCALE;
    I.x *= inv; I.y *= inv; I.z *= inv; I.w *= inv;

    float Sx = g_S[m] * inv;
    float4 Sw = reinterpret_cast<const float4*>(g_S + B_DIM)[n4];
    Sw.x *= inv; Sw.y *= inv; Sw.z *= inv; Sw.w *= inv;

    float a = *alpha;
    float b = *beta;
    float4 bs = reinterpret_cast<const float4*>(bias)[n4];

    float4 o;
    o.x = I.x / (I.x + a * (Sx - I.x) + b * (Sw.x - I.x) + EPS_T) + bs.x;
    o.y = I.y / (I.y + a * (Sx - I.y) + b * (Sw.y - I.y) + EPS_T) + bs.y;
    o.z = I.z / (I.z + a * (Sx - I.z) + b * (Sw.z - I.z) + EPS_T) + bs.z;
    o.w = I.w / (I.w + a * (Sx - I.w) + b * (Sw.w - I.w) + EPS_T) + bs.w;

    reinterpret_cast<float4*>(out)[t4] = o;
}

// ---------------------------------------------------------------------------
extern "C" void kernel_launch(void* const* d_in, const int* in_sizes, int n_in,
                              void* d_out, int out_size)
{
    const float* x      = (const float*)d_in[0];   // (512, 1024)
    const float* weight = (const float*)d_in[1];   // (512, 1024)
    const float* bias   = (const float*)d_in[2];   // (512,)
    const float* alpha  = (const float*)d_in[3];   // scalar
    const float* beta   = (const float*)d_in[4];   // scalar
    float* out = (float*)d_out;                    // (512, 512)

    prep_kernel<<<B_DIM + P_DIM, 256>>>(x, weight);
    tversky_main_kernel<<<GRID_MAIN, 256>>>();
    finalize_kernel<<<(B_DIM * P_DIM / 4) / 256, 256>>>(bias, alpha, beta, out);
}

// round 17
// speedup vs baseline: 1.1478x; 1.1478x over previous
#include <cuda_runtime.h>
#include <cuda_bf16.h>

#define B_DIM 512
#define P_DIM 512
#define F_DIM 1024
#define EPS_T 1e-8f

#define SPLITK 8
#define KC 128                      // u16 k-extent per unit
#define NTILES 64                   // 8x8 tiles of 64x64
#define NUNITS (NTILES * SPLITK)    // 512 == grid size: ONE unit per CTA
#define QSCALE 65535.0f
#define KPITCH 136                  // smem row pitch in u16 (272B, 16B-aligned)

// Scratch (static device globals — no allocation allowed)
__device__ __align__(16) unsigned short g_qx[B_DIM * F_DIM];  // u16 sigmoid(x)
__device__ __align__(16) unsigned short g_qw[P_DIM * F_DIM];  // u16 sigmoid(w)
__device__ __align__(16) float g_S[B_DIM + P_DIM];            // fp32 row sums
__device__ float g_part[SPLITK * B_DIM * P_DIM];              // split-K partials

// ---------------------------------------------------------------------------
__device__ __forceinline__ float sigmoid_fast(float x)
{
    float t;
    asm("tanh.approx.f32 %0, %1;" : "=f"(t) : "f"(x * 0.5f));
    return fmaf(0.5f, t, 0.5f);
}

__device__ __forceinline__ void cp16(void* smem_dst, const void* gsrc)
{
    unsigned sdst = (unsigned)__cvta_generic_to_shared(smem_dst);
    asm volatile("cp.async.cg.shared.global [%0], [%1], 16;"
                 :: "r"(sdst), "l"(gsrc));
}

// ---------------------------------------------------------------------------
// Kernel 1: sigmoid (tanh.approx.f32) -> u16 quantize + fp32 row sums.
// One block per row, 1024 x 256. (Best measured prep shape.)
// ---------------------------------------------------------------------------
__global__ __launch_bounds__(256) void prep_kernel(
    const float* __restrict__ x, const float* __restrict__ w)
{
    int row = blockIdx.x;                 // 0..1023 combined
    int tid = threadIdx.x;

    const float* src;
    unsigned short* dq;
    if (row < B_DIM) {
        src = x + (size_t)row * F_DIM;
        dq  = g_qx + (size_t)row * F_DIM;
    } else {
        src = w + (size_t)(row - B_DIM) * F_DIM;
        dq  = g_qw + (size_t)(row - B_DIM) * F_DIM;
    }

    float4 v = reinterpret_cast<const float4*>(src)[tid];
    float s0 = sigmoid_fast(v.x);
    float s1 = sigmoid_fast(v.y);
    float s2 = sigmoid_fast(v.z);
    float s3 = sigmoid_fast(v.w);

    unsigned q0 = __float2uint_rn(s0 * QSCALE);
    unsigned q1 = __float2uint_rn(s1 * QSCALE);
    unsigned q2 = __float2uint_rn(s2 * QSCALE);
    unsigned q3 = __float2uint_rn(s3 * QSCALE);
    reinterpret_cast<uint2*>(dq)[tid] = make_uint2(q0 | (q1 << 16), q2 | (q3 << 16));

    float local = (s0 + s1) + (s2 + s3);
    #pragma unroll
    for (int o = 16; o > 0; o >>= 1)
        local += __shfl_xor_sync(0xFFFFFFFFu, local, o);

    __shared__ float red[8];
    if ((tid & 31) == 0) red[tid >> 5] = local;
    __syncthreads();
    if (tid == 0) {
        float t = 0.f;
        #pragma unroll
        for (int i = 0; i < 8; i++) t += red[i];
        g_S[row] = t;
    }
}

// ---------------------------------------------------------------------------
// Kernel 2: ONE unit per CTA — no queue, no atomics, no double buffer.
// Unit = 64x64 output tile x KC=128 k-slice. grid 512 x 256, 4 CTAs/SM.
// Stage 32KB via cp.async, one barrier, 16 chunks of vminu2+dp2a, store.
// ---------------------------------------------------------------------------
__global__ __launch_bounds__(256, 4) void tversky_main_kernel()
{
    __shared__ __align__(16) unsigned short xs[64][KPITCH];
    __shared__ __align__(16) unsigned short ws[64][KPITCH];

    int tid = threadIdx.x;
    int tx = tid & 15;            // N: tx + 16j
    int ty = tid >> 4;            // M: ty + 16i
    int lr = tid >> 4;            // loader row base 0..15 (steps of 16)
    int sg = tid & 15;            // 16B segment within 256B row

    int u = blockIdx.x;
    int tile  = u >> 3;           // 0..63
    int split = u & 7;            // 0..7
    int m0 = (tile >> 3) << 6;
    int n0 = (tile & 7) << 6;
    int kb4 = split << 4;         // uint4 offset within 128-uint4 row

    const uint4* xg4 = reinterpret_cast<const uint4*>(g_qx);
    const uint4* wg4 = reinterpret_cast<const uint4*>(g_qw);

    // stage x tile (64 rows x 256B) + w tile: 4+4 cp.async per thread
    #pragma unroll
    for (int q = 0; q < 4; q++) {
        int row = lr + 16 * q;
        cp16(&xs[row][sg * 8], xg4 + (size_t)(m0 + row) * 128 + kb4 + sg);
        cp16(&ws[row][sg * 8], wg4 + (size_t)(n0 + row) * 128 + kb4 + sg);
    }
    asm volatile("cp.async.commit_group;" ::: "memory");
    asm volatile("cp.async.wait_group 0;" ::: "memory");
    __syncthreads();

    unsigned acc[4][4];
    #pragma unroll
    for (int i = 0; i < 4; i++)
        #pragma unroll
        for (int j = 0; j < 4; j++) acc[i][j] = 0u;

    #pragma unroll 2
    for (int c = 0; c < 16; c++) {        // 16 chunks x 8 u16 of k
        uint4 xq[4], wq[4];
        #pragma unroll
        for (int i = 0; i < 4; i++)
            xq[i] = *reinterpret_cast<const uint4*>(&xs[ty + 16 * i][c * 8]);
        #pragma unroll
        for (int j = 0; j < 4; j++)
            wq[j] = *reinterpret_cast<const uint4*>(&ws[tx + 16 * j][c * 8]);
        #pragma unroll
        for (int i = 0; i < 4; i++)
            #pragma unroll
            for (int j = 0; j < 4; j++) {
                acc[i][j] = __dp2a_lo(__vminu2(xq[i].x, wq[j].x), 0x0101u, acc[i][j]);
                acc[i][j] = __dp2a_lo(__vminu2(xq[i].y, wq[j].y), 0x0101u, acc[i][j]);
                acc[i][j] = __dp2a_lo(__vminu2(xq[i].z, wq[j].z), 0x0101u, acc[i][j]);
                acc[i][j] = __dp2a_lo(__vminu2(xq[i].w, wq[j].w), 0x0101u, acc[i][j]);
            }
    }

    // write split-K partials (exact u32 counts as fp32)
    float* pbase = g_part + ((size_t)split * B_DIM + m0) * P_DIM + n0;
    #pragma unroll
    for (int i = 0; i < 4; i++)
        #pragma unroll
        for (int j = 0; j < 4; j++)
            pbase[(size_t)(ty + 16 * i) * P_DIM + tx + 16 * j] = (float)acc[i][j];
}

// ---------------------------------------------------------------------------
// Kernel 3: combine 8 split-K partials (scale 1/65535) + Tversky epilogue.
//   out = I / (I + alpha*(Sx-I) + beta*(Sw-I) + eps) + bias
// ---------------------------------------------------------------------------
__global__ __launch_bounds__(256) void finalize_kernel(
    const float* __restrict__ bias,
    const float* __restrict__ alpha,
    const float* __restrict__ beta,
    float* __restrict__ out)
{
    int t4 = blockIdx.x * 256 + threadIdx.x;   // float4 id, 0..65535
    int m  = t4 >> 7;
    int n4 = t4 & 127;

    const float4* pp = reinterpret_cast<const float4*>(g_part) + t4;
    float4 I = make_float4(0.f, 0.f, 0.f, 0.f);
    #pragma unroll
    for (int s = 0; s < SPLITK; s++) {
        float4 v = pp[(size_t)s * (B_DIM * P_DIM / 4)];
        I.x += v.x; I.y += v.y; I.z += v.z; I.w += v.w;
    }
    const float inv = 1.0f / QSCALE;
    I.x *= inv; I.y *= inv; I.z *= inv; I.w *= inv;

    float Sx = g_S[m];
    float4 Sw = reinterpret_cast<const float4*>(g_S + B_DIM)[n4];

    float a = *alpha;
    float b = *beta;
    float4 bs = reinterpret_cast<const float4*>(bias)[n4];

    float4 o;
    o.x = I.x / (I.x + a * (Sx - I.x) + b * (Sw.x - I.x) + EPS_T) + bs.x;
    o.y = I.y / (I.y + a * (Sx - I.y) + b * (Sw.y - I.y) + EPS_T) + bs.y;
    o.z = I.z / (I.z + a * (Sx - I.z) + b * (Sw.z - I.z) + EPS_T) + bs.z;
    o.w = I.w / (I.w + a * (Sx - I.w) + b * (Sw.w - I.w) + EPS_T) + bs.w;

    reinterpret_cast<float4*>(out)[t4] = o;
}

// ---------------------------------------------------------------------------
extern "C" void kernel_launch(void* const* d_in, const int* in_sizes, int n_in,
                              void* d_out, int out_size)
{
    const float* x      = (const float*)d_in[0];   // (512, 1024)
    const float* weight = (const float*)d_in[1];   // (512, 1024)
    const float* bias   = (const float*)d_in[2];   // (512,)
    const float* alpha  = (const float*)d_in[3];   // scalar
    const float* beta   = (const float*)d_in[4];   // scalar
    float* out = (float*)d_out;                    // (512, 512)

    prep_kernel<<<B_DIM + P_DIM, 256>>>(x, weight);
    tversky_main_kernel<<<NUNITS, 256>>>();
    finalize_kernel<<<(B_DIM * P_DIM / 4) / 256, 256>>>(bias, alpha, beta, out);
}